// round 10
// baseline (speedup 1.0000x reference)
#include <cuda_runtime.h>
#include <cuda_fp16.h>
#include <cstdint>

#define N_NODES  50000
#define N_EDGES  1600000
#define IN_FEAT  256
#define HID      128
#define OUT_FEAT 256
#define K_FINAL  (IN_FEAT + HID)   // 384

// ---------------------------------------------------------------------------
// Device scratch
// ---------------------------------------------------------------------------
__device__ __half g_y   [N_NODES * HID];         // x @ W_edge, fp16 (12.8 MB)
__device__ __half g_xh  [N_NODES * IN_FEAT];     // x split hi   (25.6 MB)
__device__ __half g_xl  [N_NODES * IN_FEAT];     // x split lo
__device__ __half g_mh  [N_NODES * HID];         // msg split hi (12.8 MB)
__device__ __half g_ml  [N_NODES * HID];         // msg split lo
__device__ __half g_Bth [OUT_FEAT * K_FINAL];    // B2^T hi [256][384]
__device__ __half g_Btl [OUT_FEAT * K_FINAL];    // B2^T lo
__device__ __half g_Weth[HID * IN_FEAT];         // We^T hi [128][256]
__device__ __half g_Wetl[HID * IN_FEAT];         // We^T lo
__device__ float  g_c   [OUT_FEAT];              // folded bias
// CSR-by-dst
__device__ int    g_cnt [N_NODES];               // histogram, then cursor
__device__ int    g_off [N_NODES + 1];
__device__ int2   g_edge[N_EDGES];               // {src, w_bits}

// ---------------------------------------------------------------------------
// helpers
// ---------------------------------------------------------------------------
__device__ __forceinline__ void split_h(float v, __half& hi, __half& lo) {
    hi = __float2half_rn(v);
    lo = __float2half_rn(v - __half2float(hi));
}
__device__ __forceinline__ uint32_t packh(__half a, __half b) {
    __half2 h2 = __halves2half2(a, b);
    return *(uint32_t*)&h2;
}
__device__ __forceinline__ uint32_t smem_u32(const void* p) {
    uint32_t a;
    asm("{ .reg .u64 t; cvta.to.shared.u64 t, %1; cvt.u32.u64 %0, t; }"
        : "=r"(a) : "l"(p));
    return a;
}
#define CP_ASYNC16(dst, src, sz) \
    asm volatile("cp.async.cg.shared.global [%0], [%1], 16, %2;" \
                 :: "r"(dst), "l"(src), "r"(sz) : "memory")
#define CP_COMMIT()  asm volatile("cp.async.commit_group;" ::: "memory")
#define CP_WAIT1()   asm volatile("cp.async.wait_group 1;"  ::: "memory")

// ---------------------------------------------------------------------------
// CSR build: zero -> hist -> scan -> scatter
// ---------------------------------------------------------------------------
__global__ void zero_cnt_kernel() {
    int i = blockIdx.x * blockDim.x + threadIdx.x;
    if (i < N_NODES) g_cnt[i] = 0;
}

__global__ void hist_kernel(const int* __restrict__ dst) {
    int e = blockIdx.x * blockDim.x + threadIdx.x;
    if (e < N_EDGES) atomicAdd(&g_cnt[dst[e]], 1);
}

__global__ __launch_bounds__(1024) void scan_kernel() {
    __shared__ int part[1024];
    const int tid = threadIdx.x;
    const int C = (N_NODES + 1023) / 1024;          // 49
    const int base = tid * C;
    int s = 0;
    for (int j = 0; j < C; ++j) {
        int i = base + j;
        if (i < N_NODES) s += g_cnt[i];
    }
    part[tid] = s;
    __syncthreads();
    for (int d = 1; d < 1024; d <<= 1) {            // Hillis-Steele inclusive
        int v = 0;
        if (tid >= d) v = part[tid - d];
        __syncthreads();
        if (tid >= d) part[tid] += v;
        __syncthreads();
    }
    int run = (tid == 0) ? 0 : part[tid - 1];
    for (int j = 0; j < C; ++j) {
        int i = base + j;
        if (i < N_NODES) {
            int c = g_cnt[i];
            g_off[i] = run;
            g_cnt[i] = run;                          // cursor for scatter
            run += c;
        }
    }
    if (tid == 0) g_off[N_NODES] = part[1023];
}

__global__ void scatter_kernel(const int* __restrict__ src,
                               const int* __restrict__ dst,
                               const float* __restrict__ w) {
    int e = blockIdx.x * blockDim.x + threadIdx.x;
    if (e >= N_EDGES) return;
    int d = dst[e];
    int p = atomicAdd(&g_cnt[d], 1);
    g_edge[p] = make_int2(src[e], __float_as_int(w[e]));
}

// ---------------------------------------------------------------------------
// pre-split x into fp16 hi/lo
// ---------------------------------------------------------------------------
__global__ void split_x_kernel(const float4* __restrict__ x4) {
    int i = blockIdx.x * blockDim.x + threadIdx.x;
    if (i >= N_NODES * IN_FEAT / 4) return;
    float4 v = x4[i];
    __half h0, l0, h1, l1, h2, l2, h3, l3;
    split_h(v.x, h0, l0); split_h(v.y, h1, l1);
    split_h(v.z, h2, l2); split_h(v.w, h3, l3);
    uint2 H = make_uint2(packh(h0, h1), packh(h2, h3));
    uint2 L = make_uint2(packh(l0, l1), packh(l2, l3));
    *(uint2*)&g_xh[i * 4] = H;
    *(uint2*)&g_xl[i * 4] = L;
}

// ---------------------------------------------------------------------------
// fold weights (transposed + fp16-split)
// ---------------------------------------------------------------------------
__global__ void fold_b2t_kernel(const float* __restrict__ Wn,
                                const float* __restrict__ bn,
                                const float* __restrict__ be,
                                const float* __restrict__ Wm,
                                const float* __restrict__ bm) {
    __shared__ float sWm[HID];
    int n = blockIdx.x;
    int k = threadIdx.x;                 // 0..383
    if (k < HID) sWm[k] = Wm[(size_t)k * OUT_FEAT + n];
    __syncthreads();

    float val;
    if (k < IN_FEAT) {
        const float* wr = Wn + (size_t)k * HID;
        float acc = 0.f;
        #pragma unroll 4
        for (int j = 0; j < HID; ++j) acc = fmaf(wr[j], sWm[j], acc);
        val = acc;
    } else {
        val = sWm[k - IN_FEAT];
    }
    __half h, l;
    split_h(val, h, l);
    g_Bth[(size_t)n * K_FINAL + k] = h;
    g_Btl[(size_t)n * K_FINAL + k] = l;

    if (k == 0) {
        float acc = bm[n];
        for (int j = 0; j < HID; ++j) acc = fmaf(bn[j] + be[j], sWm[j], acc);
        g_c[n] = acc;
    }
}

__global__ void fold_wet_kernel(const float* __restrict__ We) {
    int idx = blockIdx.x * blockDim.x + threadIdx.x;
    if (idx >= IN_FEAT * HID) return;
    int k = idx >> 7;
    int h = idx & (HID - 1);
    float v = We[idx];
    __half hh, hl;
    split_h(v, hh, hl);
    g_Weth[(size_t)h * IN_FEAT + k] = hh;
    g_Wetl[(size_t)h * IN_FEAT + k] = hl;
}

// ---------------------------------------------------------------------------
// CSR aggregation: one warp per node, register accumulation, no atomics.
// y is fp16: warp gathers 128 halfs (256B) per edge, fp32 accumulate.
// Output split fp16 hi/lo for the final GEMM.
// ---------------------------------------------------------------------------
__global__ __launch_bounds__(256) void agg_csr_kernel() {
    int v    = (blockIdx.x * blockDim.x + threadIdx.x) >> 5;
    int lane = threadIdx.x & 31;
    if (v >= N_NODES) return;

    int b  = g_off[v];
    int e2 = g_off[v + 1];
    const __half2* yb = (const __half2*)g_y;   // 64 half2 per row

    float4 acc = make_float4(0.f, 0.f, 0.f, 0.f);
    int i = b;
    for (; i + 2 <= e2; i += 2) {
        int2 ea = g_edge[i];
        int2 eb = g_edge[i + 1];
        float w0 = __int_as_float(ea.y);
        float w1 = __int_as_float(eb.y);
        // lane covers half2 pair [lane*2, lane*2+1]  (4 halfs = 8B, coalesced)
        const __half2* p0 = yb + (size_t)ea.x * 64 + lane * 2;
        const __half2* p1 = yb + (size_t)eb.x * 64 + lane * 2;
        __half2 a0 = p0[0], a1 = p0[1];
        __half2 b0 = p1[0], b1 = p1[1];
        float2 fa0 = __half22float2(a0), fa1 = __half22float2(a1);
        float2 fb0 = __half22float2(b0), fb1 = __half22float2(b1);
        acc.x += fa0.x * w0 + fb0.x * w1;
        acc.y += fa0.y * w0 + fb0.y * w1;
        acc.z += fa1.x * w0 + fb1.x * w1;
        acc.w += fa1.y * w0 + fb1.y * w1;
    }
    if (i < e2) {
        int2 ea = g_edge[i];
        float w0 = __int_as_float(ea.y);
        const __half2* p0 = yb + (size_t)ea.x * 64 + lane * 2;
        float2 fa0 = __half22float2(p0[0]);
        float2 fa1 = __half22float2(p0[1]);
        acc.x += fa0.x * w0; acc.y += fa0.y * w0;
        acc.z += fa1.x * w0; acc.w += fa1.y * w0;
    }

    __half h0, l0, h1, l1, h2, l2, h3, l3;
    split_h(acc.x, h0, l0); split_h(acc.y, h1, l1);
    split_h(acc.z, h2, l2); split_h(acc.w, h3, l3);
    uint2 H = make_uint2(packh(h0, h1), packh(h2, h3));
    uint2 L = make_uint2(packh(l0, l1), packh(l2, l3));
    *(uint2*)&g_mh[(size_t)v * HID + lane * 4] = H;
    *(uint2*)&g_ml[(size_t)v * HID + lane * 4] = L;
}

// ---------------------------------------------------------------------------
// split-precision fp16 GEMM, cp.async double-buffered.
// C[M x NOUT] = [A0 | A1] @ Bt^T (+ bias); all operands pre-split fp16.
// OUTH: write fp16 output (for y), else fp32.
// BM=128, BN=128, BK=32; 256 threads; warp tile 32x64; mma.m16n8k16.
// ---------------------------------------------------------------------------
#define MMA_F16(C, A, B0, B1)                                               \
    asm volatile(                                                           \
        "mma.sync.aligned.m16n8k16.row.col.f32.f16.f16.f32 "                \
        "{%0,%1,%2,%3}, {%4,%5,%6,%7}, {%8,%9}, {%0,%1,%2,%3};"             \
        : "+f"((C)[0]), "+f"((C)[1]), "+f"((C)[2]), "+f"((C)[3])            \
        : "r"((A)[0]), "r"((A)[1]), "r"((A)[2]), "r"((A)[3]),               \
          "r"(B0), "r"(B1))

#define STAGE_BYTES 40960
#define GEMM_SMEM   (2 * STAGE_BYTES)

template<int KTOT, int NOUT, bool CONCAT, bool BIAS, bool OUTH>
__global__ __launch_bounds__(256) void gemm_f16_kernel(
    const __half* __restrict__ A0h, const __half* __restrict__ A0l,  // [M x IN_FEAT]
    const __half* __restrict__ A1h, const __half* __restrict__ A1l,  // [M x HID]
    const __half* __restrict__ Bh,  const __half* __restrict__ Bl,   // [NOUT x KTOT]
    const float*  __restrict__ bias,
    void*         __restrict__ Cv,
    int M) {
    extern __shared__ uint32_t sm[];
    const uint32_t smb = smem_u32(sm);

    const int tid  = threadIdx.x;
    const int brow = blockIdx.y * 128;
    const int bcol = blockIdx.x * 128;

    const int warp = tid >> 5, lane = tid & 31;
    const int g = lane >> 2, tg = lane & 3;
    const int wm = warp >> 1, wn = warp & 1;

    constexpr int T = KTOT / 32;

    float acc[2][8][4];
    #pragma unroll
    for (int mt = 0; mt < 2; ++mt)
        #pragma unroll
        for (int nt = 0; nt < 8; ++nt)
            #pragma unroll
            for (int i = 0; i < 4; ++i) acc[mt][nt][i] = 0.f;

    auto issue = [&](int t) {
        const int s  = t & 1;
        const uint32_t sb = smb + s * STAGE_BYTES;
        const int k0 = t * 32;
        #pragma unroll
        for (int i = 0; i < 2; ++i) {
            int ch = tid + i * 256;       // 0..511
            int m = ch >> 2, c = ch & 3;
            // ---- A ----
            int r = brow + m;
            uint32_t sz = (r < M) ? 16u : 0u;
            int rc = (r < M) ? r : (M - 1);
            const __half *pH, *pL;
            if (!CONCAT || k0 < IN_FEAT) {
                size_t o = (size_t)rc * IN_FEAT + k0 + c * 8;
                pH = A0h + o; pL = A0l + o;
            } else {
                size_t o = (size_t)rc * HID + (k0 - IN_FEAT) + c * 8;
                pH = A1h + o; pL = A1l + o;
            }
            uint32_t da = sb + (uint32_t)(m * 20 + c * 4) * 4;
            CP_ASYNC16(da,          pH, sz);
            CP_ASYNC16(da + 10240,  pL, sz);
            // ---- B ----
            int n = bcol + m;
            size_t ob = (size_t)n * KTOT + k0 + c * 8;
            CP_ASYNC16(da + 20480, Bh + ob, 16u);
            CP_ASYNC16(da + 30720, Bl + ob, 16u);
        }
    };

    issue(0); CP_COMMIT();
    if (T > 1) issue(1);
    CP_COMMIT();

    for (int t = 0; t < T; ++t) {
        CP_WAIT1();
        __syncthreads();

        const uint32_t* Ash = sm + (t & 1) * (STAGE_BYTES / 4);
        const uint32_t* Asl = Ash + 2560;
        const uint32_t* Bsh = Ash + 5120;
        const uint32_t* Bsl = Ash + 7680;

        #pragma unroll
        for (int ks2 = 0; ks2 < 2; ++ks2) {
            const int kb = ks2 * 8;
            uint32_t afh[2][4], afl[2][4];
            #pragma unroll
            for (int mt = 0; mt < 2; ++mt) {
                int m0 = wm * 32 + mt * 16 + g;
                int o00 = m0 * 20 + kb + tg;
                int o10 = (m0 + 8) * 20 + kb + tg;
                afh[mt][0] = Ash[o00];     afl[mt][0] = Asl[o00];
                afh[mt][1] = Ash[o10];     afl[mt][1] = Asl[o10];
                afh[mt][2] = Ash[o00 + 4]; afl[mt][2] = Asl[o00 + 4];
                afh[mt][3] = Ash[o10 + 4]; afl[mt][3] = Asl[o10 + 4];
            }
            #pragma unroll
            for (int nt = 0; nt < 8; ++nt) {
                int n = wn * 64 + nt * 8 + g;
                int ob = n * 20 + kb + tg;
                uint32_t bh0 = Bsh[ob], bh1 = Bsh[ob + 4];
                uint32_t bl0 = Bsl[ob], bl1 = Bsl[ob + 4];
                #pragma unroll
                for (int mt = 0; mt < 2; ++mt) {
                    MMA_F16(acc[mt][nt], afh[mt], bh0, bh1);
                    MMA_F16(acc[mt][nt], afl[mt], bh0, bh1);
                    MMA_F16(acc[mt][nt], afh[mt], bl0, bl1);
                }
            }
        }
        __syncthreads();
        if (t + 2 < T) issue(t + 2);
        CP_COMMIT();
    }

    // ---- epilogue ----
    #pragma unroll
    for (int mt = 0; mt < 2; ++mt) {
        int row0 = brow + wm * 32 + mt * 16 + g;
        int row1 = row0 + 8;
        #pragma unroll
        for (int nt = 0; nt < 8; ++nt) {
            int col = bcol + wn * 64 + nt * 8 + tg * 2;
            float b0 = BIAS ? bias[col]     : 0.f;
            float b1 = BIAS ? bias[col + 1] : 0.f;
            if (OUTH) {
                __half* C = (__half*)Cv;
                if (row0 < M)
                    *(__half2*)(C + (size_t)row0 * NOUT + col) =
                        __floats2half2_rn(acc[mt][nt][0] + b0, acc[mt][nt][1] + b1);
                if (row1 < M)
                    *(__half2*)(C + (size_t)row1 * NOUT + col) =
                        __floats2half2_rn(acc[mt][nt][2] + b0, acc[mt][nt][3] + b1);
            } else {
                float* C = (float*)Cv;
                if (row0 < M) {
                    float2 o = make_float2(acc[mt][nt][0] + b0, acc[mt][nt][1] + b1);
                    *(float2*)(C + (size_t)row0 * NOUT + col) = o;
                }
                if (row1 < M) {
                    float2 o = make_float2(acc[mt][nt][2] + b0, acc[mt][nt][3] + b1);
                    *(float2*)(C + (size_t)row1 * NOUT + col) = o;
                }
            }
        }
    }
}

// ---------------------------------------------------------------------------
// launch
// ---------------------------------------------------------------------------
extern "C" void kernel_launch(void* const* d_in, const int* in_sizes, int n_in,
                              void* d_out, int out_size) {
    const float* x   = (const float*)d_in[0];
    const float* w   = (const float*)d_in[1];
    const int*   src = (const int*)  d_in[2];
    const int*   dst = (const int*)  d_in[3];
    const float* Wn  = (const float*)d_in[4];
    const float* bn  = (const float*)d_in[5];
    const float* We  = (const float*)d_in[6];
    const float* be  = (const float*)d_in[7];
    const float* Wm  = (const float*)d_in[8];
    const float* bm  = (const float*)d_in[9];
    float*       out = (float*)d_out;

    float *cvec;
    __half *y, *xh, *xl, *mh, *ml, *Bth, *Btl, *Weth, *Wetl;
    cudaGetSymbolAddress((void**)&y,    g_y);
    cudaGetSymbolAddress((void**)&cvec, g_c);
    cudaGetSymbolAddress((void**)&xh,   g_xh);
    cudaGetSymbolAddress((void**)&xl,   g_xl);
    cudaGetSymbolAddress((void**)&mh,   g_mh);
    cudaGetSymbolAddress((void**)&ml,   g_ml);
    cudaGetSymbolAddress((void**)&Bth,  g_Bth);
    cudaGetSymbolAddress((void**)&Btl,  g_Btl);
    cudaGetSymbolAddress((void**)&Weth, g_Weth);
    cudaGetSymbolAddress((void**)&Wetl, g_Wetl);

    cudaFuncSetAttribute(gemm_f16_kernel<IN_FEAT, HID, false, false, true>,
                         cudaFuncAttributeMaxDynamicSharedMemorySize, GEMM_SMEM);
    cudaFuncSetAttribute(gemm_f16_kernel<K_FINAL, OUT_FEAT, true, true, false>,
                         cudaFuncAttributeMaxDynamicSharedMemorySize, GEMM_SMEM);

    // CSR build
    zero_cnt_kernel<<<(N_NODES + 255) / 256, 256>>>();
    hist_kernel<<<(N_EDGES + 255) / 256, 256>>>(dst);
    scan_kernel<<<1, 1024>>>();
    scatter_kernel<<<(N_EDGES + 255) / 256, 256>>>(src, dst, w);

    // pre-split x; fold weights
    split_x_kernel<<<(N_NODES * IN_FEAT / 4 + 255) / 256, 256>>>((const float4*)x);
    fold_b2t_kernel<<<OUT_FEAT, K_FINAL>>>(Wn, bn, be, Wm, bm);
    fold_wet_kernel<<<(IN_FEAT * HID + 255) / 256, 256>>>(We);

    // y = x @ W_edge   [50000 x 128] fp16 out
    {
        dim3 grid(1, (N_NODES + 127) / 128);
        gemm_f16_kernel<IN_FEAT, HID, false, false, true>
            <<<grid, 256, GEMM_SMEM>>>(xh, xl, nullptr, nullptr,
                                       Weth, Wetl, nullptr, y, N_NODES);
    }

    // msg aggregation (CSR, no atomics, fp16 gather) -> split fp16
    agg_csr_kernel<<<(N_NODES * 32 + 255) / 256, 256>>>();

    // out = [x | msg] @ B2 + c   [50000 x 256] fp32 out
    {
        dim3 grid(OUT_FEAT / 128, (N_NODES + 127) / 128);
        gemm_f16_kernel<K_FINAL, OUT_FEAT, true, true, false>
            <<<grid, 256, GEMM_SMEM>>>(xh, xl, mh, ml,
                                       Bth, Btl, cvec, out, N_NODES);
    }
}

// round 11
// speedup vs baseline: 1.7287x; 1.7287x over previous
#include <cuda_runtime.h>
#include <cuda_fp16.h>
#include <cstdint>

#define N_NODES  50000
#define N_EDGES  1600000
#define IN_FEAT  256
#define HID      128
#define OUT_FEAT 256
#define N_YZ     256              // [y | z] width

// ---------------------------------------------------------------------------
// Device scratch
// ---------------------------------------------------------------------------
__device__ float  g_yz  [N_NODES * N_YZ];        // [y|z] fp32 (51.2 MB)
__device__ __half g_xh  [N_NODES * IN_FEAT];     // x split hi
__device__ __half g_xl  [N_NODES * IN_FEAT];     // x split lo
__device__ __half g_hh  [N_NODES * HID];         // h split hi
__device__ __half g_hl  [N_NODES * HID];         // h split lo
__device__ __half g_W1th[N_YZ * IN_FEAT];        // [We|Wn]^T hi  [256][256]
__device__ __half g_W1tl[N_YZ * IN_FEAT];        // [We|Wn]^T lo
__device__ __half g_W2th[OUT_FEAT * HID];        // Wm^T hi       [256][128]
__device__ __half g_W2tl[OUT_FEAT * HID];        // Wm^T lo
__device__ float  g_hb  [HID];                   // b_node + b_edge
// CSR-by-dst
__device__ int    g_cnt [N_NODES];               // histogram, then cursor
__device__ int    g_off [N_NODES + 1];
__device__ int2   g_edge[N_EDGES];               // {src, w_bits}

// ---------------------------------------------------------------------------
// helpers
// ---------------------------------------------------------------------------
__device__ __forceinline__ void split_h(float v, __half& hi, __half& lo) {
    hi = __float2half_rn(v);
    lo = __float2half_rn(v - __half2float(hi));
}
__device__ __forceinline__ uint32_t packh(__half a, __half b) {
    __half2 h2 = __halves2half2(a, b);
    return *(uint32_t*)&h2;
}
__device__ __forceinline__ uint32_t smem_u32(const void* p) {
    uint32_t a;
    asm("{ .reg .u64 t; cvta.to.shared.u64 t, %1; cvt.u32.u64 %0, t; }"
        : "=r"(a) : "l"(p));
    return a;
}
#define CP_ASYNC16(dst, src, sz) \
    asm volatile("cp.async.cg.shared.global [%0], [%1], 16, %2;" \
                 :: "r"(dst), "l"(src), "r"(sz) : "memory")
#define CP_COMMIT()  asm volatile("cp.async.commit_group;" ::: "memory")
#define CP_WAIT1()   asm volatile("cp.async.wait_group 1;"  ::: "memory")

// ---------------------------------------------------------------------------
// CSR build: zero -> hist -> scan -> scatter
// ---------------------------------------------------------------------------
__global__ void zero_cnt_kernel() {
    int i = blockIdx.x * blockDim.x + threadIdx.x;
    if (i < N_NODES) g_cnt[i] = 0;
}

__global__ void hist_kernel(const int* __restrict__ dst) {
    int e = blockIdx.x * blockDim.x + threadIdx.x;
    if (e < N_EDGES) atomicAdd(&g_cnt[dst[e]], 1);
}

__global__ __launch_bounds__(1024) void scan_kernel() {
    __shared__ int part[1024];
    const int tid = threadIdx.x;
    const int C = (N_NODES + 1023) / 1024;          // 49
    const int base = tid * C;
    int s = 0;
    for (int j = 0; j < C; ++j) {
        int i = base + j;
        if (i < N_NODES) s += g_cnt[i];
    }
    part[tid] = s;
    __syncthreads();
    for (int d = 1; d < 1024; d <<= 1) {            // Hillis-Steele inclusive
        int v = 0;
        if (tid >= d) v = part[tid - d];
        __syncthreads();
        if (tid >= d) part[tid] += v;
        __syncthreads();
    }
    int run = (tid == 0) ? 0 : part[tid - 1];
    for (int j = 0; j < C; ++j) {
        int i = base + j;
        if (i < N_NODES) {
            int c = g_cnt[i];
            g_off[i] = run;
            g_cnt[i] = run;                          // cursor for scatter
            run += c;
        }
    }
    if (tid == 0) g_off[N_NODES] = part[1023];
}

__global__ void scatter_kernel(const int* __restrict__ src,
                               const int* __restrict__ dst,
                               const float* __restrict__ w) {
    int e = blockIdx.x * blockDim.x + threadIdx.x;
    if (e >= N_EDGES) return;
    int d = dst[e];
    int p = atomicAdd(&g_cnt[d], 1);
    g_edge[p] = make_int2(src[e], __float_as_int(w[e]));
}

// ---------------------------------------------------------------------------
// pre-split x into fp16 hi/lo
// ---------------------------------------------------------------------------
__global__ void split_x_kernel(const float4* __restrict__ x4) {
    int i = blockIdx.x * blockDim.x + threadIdx.x;
    if (i >= N_NODES * IN_FEAT / 4) return;
    float4 v = x4[i];
    __half h0, l0, h1, l1, h2, l2, h3, l3;
    split_h(v.x, h0, l0); split_h(v.y, h1, l1);
    split_h(v.z, h2, l2); split_h(v.w, h3, l3);
    uint2 H = make_uint2(packh(h0, h1), packh(h2, h3));
    uint2 L = make_uint2(packh(l0, l1), packh(l2, l3));
    *(uint2*)&g_xh[i * 4] = H;
    *(uint2*)&g_xl[i * 4] = L;
}

// ---------------------------------------------------------------------------
// weight transposes (fp16-split); no heavy folding needed anymore
//   W1t[n][k] = n<128 ? We[k][n] : Wn[k][n-128]     (k in 0..255)
//   W2t[n][k] = Wm[k][n]                            (k in 0..127)
//   hb[j]     = bn[j] + be[j]
// ---------------------------------------------------------------------------
__global__ void fold_w1t_kernel(const float* __restrict__ We,
                                const float* __restrict__ Wn) {
    int idx = blockIdx.x * blockDim.x + threadIdx.x;
    if (idx >= N_YZ * IN_FEAT) return;
    int n = idx >> 8;            // 0..255
    int k = idx & 255;           // 0..255
    float v = (n < HID) ? We[(size_t)k * HID + n]
                        : Wn[(size_t)k * HID + (n - HID)];
    __half h, l;
    split_h(v, h, l);
    g_W1th[(size_t)n * IN_FEAT + k] = h;
    g_W1tl[(size_t)n * IN_FEAT + k] = l;
}

__global__ void fold_w2t_kernel(const float* __restrict__ Wm,
                                const float* __restrict__ bn,
                                const float* __restrict__ be) {
    int idx = blockIdx.x * blockDim.x + threadIdx.x;
    if (idx < OUT_FEAT * HID) {
        int n = idx >> 7;        // 0..255
        int k = idx & 127;       // 0..127
        float v = Wm[(size_t)k * OUT_FEAT + n];
        __half h, l;
        split_h(v, h, l);
        g_W2th[(size_t)n * HID + k] = h;
        g_W2tl[(size_t)n * HID + k] = l;
    }
    if (idx < HID) g_hb[idx] = bn[idx] + be[idx];
}

// ---------------------------------------------------------------------------
// CSR aggregation + h fusion: one warp per node, no atomics.
//   h[v] = z[v] + sum_e y[src_e]*w_e + hb ;  output split fp16 hi/lo
// y = g_yz cols 0..127 (fp32, float4/lane), z = cols 128..255.
// ---------------------------------------------------------------------------
__global__ __launch_bounds__(256) void agg_csr_kernel() {
    int v    = (blockIdx.x * blockDim.x + threadIdx.x) >> 5;
    int lane = threadIdx.x & 31;
    if (v >= N_NODES) return;

    int b  = g_off[v];
    int e2 = g_off[v + 1];
    const float4* yb = (const float4*)g_yz;   // row = 64 float4; y = first 32

    float4 acc = make_float4(0.f, 0.f, 0.f, 0.f);
    int i = b;
    for (; i + 2 <= e2; i += 2) {
        int2 ea = g_edge[i];
        int2 eb = g_edge[i + 1];
        float w0 = __int_as_float(ea.y);
        float w1 = __int_as_float(eb.y);
        float4 t0 = yb[(size_t)ea.x * 64 + lane];
        float4 t1 = yb[(size_t)eb.x * 64 + lane];
        acc.x += t0.x * w0 + t1.x * w1;
        acc.y += t0.y * w0 + t1.y * w1;
        acc.z += t0.z * w0 + t1.z * w1;
        acc.w += t0.w * w0 + t1.w * w1;
    }
    if (i < e2) {
        int2 ea = g_edge[i];
        float w0 = __int_as_float(ea.y);
        float4 t0 = yb[(size_t)ea.x * 64 + lane];
        acc.x += t0.x * w0; acc.y += t0.y * w0;
        acc.z += t0.z * w0; acc.w += t0.w * w0;
    }

    float4 zv = yb[(size_t)v * 64 + 32 + lane];
    float4 hb = ((const float4*)g_hb)[lane];
    acc.x += zv.x + hb.x;
    acc.y += zv.y + hb.y;
    acc.z += zv.z + hb.z;
    acc.w += zv.w + hb.w;

    __half h0, l0, h1, l1, h2, l2, h3, l3;
    split_h(acc.x, h0, l0); split_h(acc.y, h1, l1);
    split_h(acc.z, h2, l2); split_h(acc.w, h3, l3);
    uint2 H = make_uint2(packh(h0, h1), packh(h2, h3));
    uint2 L = make_uint2(packh(l0, l1), packh(l2, l3));
    *(uint2*)&g_hh[(size_t)v * HID + lane * 4] = H;
    *(uint2*)&g_hl[(size_t)v * HID + lane * 4] = L;
}

// ---------------------------------------------------------------------------
// split-precision fp16 GEMM, cp.async double-buffered (R9-validated core).
// C[M x NOUT] = A @ Bt^T (+ bias); A,Bt pre-split fp16; A row stride = KTOT.
// BM=128, BN=128, BK=32; 256 threads; warp tile 32x64; mma.m16n8k16.
// ---------------------------------------------------------------------------
#define MMA_F16(C, A, B0, B1)                                               \
    asm volatile(                                                           \
        "mma.sync.aligned.m16n8k16.row.col.f32.f16.f16.f32 "                \
        "{%0,%1,%2,%3}, {%4,%5,%6,%7}, {%8,%9}, {%0,%1,%2,%3};"             \
        : "+f"((C)[0]), "+f"((C)[1]), "+f"((C)[2]), "+f"((C)[3])            \
        : "r"((A)[0]), "r"((A)[1]), "r"((A)[2]), "r"((A)[3]),               \
          "r"(B0), "r"(B1))

#define STAGE_BYTES 40960
#define GEMM_SMEM   (2 * STAGE_BYTES)

template<int KTOT, int NOUT, bool BIAS>
__global__ __launch_bounds__(256) void gemm_f16_kernel(
    const __half* __restrict__ Ah, const __half* __restrict__ Al,   // [M x KTOT]
    const __half* __restrict__ Bh, const __half* __restrict__ Bl,   // [NOUT x KTOT]
    const float*  __restrict__ bias,
    float*        __restrict__ C,
    int M) {
    extern __shared__ uint32_t sm[];
    const uint32_t smb = smem_u32(sm);

    const int tid  = threadIdx.x;
    const int brow = blockIdx.y * 128;
    const int bcol = blockIdx.x * 128;

    const int warp = tid >> 5, lane = tid & 31;
    const int g = lane >> 2, tg = lane & 3;
    const int wm = warp >> 1, wn = warp & 1;

    constexpr int T = KTOT / 32;

    float acc[2][8][4];
    #pragma unroll
    for (int mt = 0; mt < 2; ++mt)
        #pragma unroll
        for (int nt = 0; nt < 8; ++nt)
            #pragma unroll
            for (int i = 0; i < 4; ++i) acc[mt][nt][i] = 0.f;

    auto issue = [&](int t) {
        const int s  = t & 1;
        const uint32_t sb = smb + s * STAGE_BYTES;
        const int k0 = t * 32;
        #pragma unroll
        for (int i = 0; i < 2; ++i) {
            int ch = tid + i * 256;       // 0..511
            int m = ch >> 2, c = ch & 3;
            // ---- A ----
            int r = brow + m;
            uint32_t sz = (r < M) ? 16u : 0u;
            int rc = (r < M) ? r : (M - 1);
            size_t oa = (size_t)rc * KTOT + k0 + c * 8;
            uint32_t da = sb + (uint32_t)(m * 20 + c * 4) * 4;
            CP_ASYNC16(da,          Ah + oa, sz);
            CP_ASYNC16(da + 10240,  Al + oa, sz);
            // ---- B ----
            int n = bcol + m;
            size_t ob = (size_t)n * KTOT + k0 + c * 8;
            CP_ASYNC16(da + 20480, Bh + ob, 16u);
            CP_ASYNC16(da + 30720, Bl + ob, 16u);
        }
    };

    issue(0); CP_COMMIT();
    if (T > 1) issue(1);
    CP_COMMIT();

    for (int t = 0; t < T; ++t) {
        CP_WAIT1();
        __syncthreads();

        const uint32_t* Ash = sm + (t & 1) * (STAGE_BYTES / 4);
        const uint32_t* Asl = Ash + 2560;
        const uint32_t* Bsh = Ash + 5120;
        const uint32_t* Bsl = Ash + 7680;

        #pragma unroll
        for (int ks2 = 0; ks2 < 2; ++ks2) {
            const int kb = ks2 * 8;
            uint32_t afh[2][4], afl[2][4];
            #pragma unroll
            for (int mt = 0; mt < 2; ++mt) {
                int m0 = wm * 32 + mt * 16 + g;
                int o00 = m0 * 20 + kb + tg;
                int o10 = (m0 + 8) * 20 + kb + tg;
                afh[mt][0] = Ash[o00];     afl[mt][0] = Asl[o00];
                afh[mt][1] = Ash[o10];     afl[mt][1] = Asl[o10];
                afh[mt][2] = Ash[o00 + 4]; afl[mt][2] = Asl[o00 + 4];
                afh[mt][3] = Ash[o10 + 4]; afl[mt][3] = Asl[o10 + 4];
            }
            #pragma unroll
            for (int nt = 0; nt < 8; ++nt) {
                int n = wn * 64 + nt * 8 + g;
                int ob = n * 20 + kb + tg;
                uint32_t bh0 = Bsh[ob], bh1 = Bsh[ob + 4];
                uint32_t bl0 = Bsl[ob], bl1 = Bsl[ob + 4];
                #pragma unroll
                for (int mt = 0; mt < 2; ++mt) {
                    MMA_F16(acc[mt][nt], afh[mt], bh0, bh1);
                    MMA_F16(acc[mt][nt], afl[mt], bh0, bh1);
                    MMA_F16(acc[mt][nt], afh[mt], bl0, bl1);
                }
            }
        }
        __syncthreads();
        if (t + 2 < T) issue(t + 2);
        CP_COMMIT();
    }

    // ---- epilogue (fp32) ----
    #pragma unroll
    for (int mt = 0; mt < 2; ++mt) {
        int row0 = brow + wm * 32 + mt * 16 + g;
        int row1 = row0 + 8;
        #pragma unroll
        for (int nt = 0; nt < 8; ++nt) {
            int col = bcol + wn * 64 + nt * 8 + tg * 2;
            float b0 = BIAS ? bias[col]     : 0.f;
            float b1 = BIAS ? bias[col + 1] : 0.f;
            if (row0 < M) {
                float2 o = make_float2(acc[mt][nt][0] + b0, acc[mt][nt][1] + b1);
                *(float2*)(C + (size_t)row0 * NOUT + col) = o;
            }
            if (row1 < M) {
                float2 o = make_float2(acc[mt][nt][2] + b0, acc[mt][nt][3] + b1);
                *(float2*)(C + (size_t)row1 * NOUT + col) = o;
            }
        }
    }
}

// ---------------------------------------------------------------------------
// launch
// ---------------------------------------------------------------------------
extern "C" void kernel_launch(void* const* d_in, const int* in_sizes, int n_in,
                              void* d_out, int out_size) {
    const float* x   = (const float*)d_in[0];
    const float* w   = (const float*)d_in[1];
    const int*   src = (const int*)  d_in[2];
    const int*   dst = (const int*)  d_in[3];
    const float* Wn  = (const float*)d_in[4];
    const float* bn  = (const float*)d_in[5];
    const float* We  = (const float*)d_in[6];
    const float* be  = (const float*)d_in[7];
    const float* Wm  = (const float*)d_in[8];
    const float* bm  = (const float*)d_in[9];
    float*       out = (float*)d_out;

    float *yz;
    __half *xh, *xl, *hh, *hl, *W1th, *W1tl, *W2th, *W2tl;
    cudaGetSymbolAddress((void**)&yz,   g_yz);
    cudaGetSymbolAddress((void**)&xh,   g_xh);
    cudaGetSymbolAddress((void**)&xl,   g_xl);
    cudaGetSymbolAddress((void**)&hh,   g_hh);
    cudaGetSymbolAddress((void**)&hl,   g_hl);
    cudaGetSymbolAddress((void**)&W1th, g_W1th);
    cudaGetSymbolAddress((void**)&W1tl, g_W1tl);
    cudaGetSymbolAddress((void**)&W2th, g_W2th);
    cudaGetSymbolAddress((void**)&W2tl, g_W2tl);

    cudaFuncSetAttribute(gemm_f16_kernel<IN_FEAT, N_YZ, false>,
                         cudaFuncAttributeMaxDynamicSharedMemorySize, GEMM_SMEM);
    cudaFuncSetAttribute(gemm_f16_kernel<HID, OUT_FEAT, true>,
                         cudaFuncAttributeMaxDynamicSharedMemorySize, GEMM_SMEM);

    // CSR build
    zero_cnt_kernel<<<(N_NODES + 255) / 256, 256>>>();
    hist_kernel<<<(N_EDGES + 255) / 256, 256>>>(dst);
    scan_kernel<<<1, 1024>>>();
    scatter_kernel<<<(N_EDGES + 255) / 256, 256>>>(src, dst, w);

    // pre-split x; transpose+split weights
    split_x_kernel<<<(N_NODES * IN_FEAT / 4 + 255) / 256, 256>>>((const float4*)x);
    fold_w1t_kernel<<<(N_YZ * IN_FEAT + 255) / 256, 256>>>(We, Wn);
    fold_w2t_kernel<<<(OUT_FEAT * HID + 255) / 256, 256>>>(Wm, bn, be);

    // GEMM1: [y|z] = x @ [We|Wn]   [50000 x 256] fp32
    {
        dim3 grid(N_YZ / 128, (N_NODES + 127) / 128);
        gemm_f16_kernel<IN_FEAT, N_YZ, false>
            <<<grid, 256, GEMM_SMEM>>>(xh, xl, W1th, W1tl, nullptr, yz, N_NODES);
    }

    // agg: h = z + sum y[src]*w + (bn+be)  -> split fp16
    agg_csr_kernel<<<(N_NODES * 32 + 255) / 256, 256>>>();

    // GEMM2: out = h @ Wm + bm   [50000 x 256] fp32
    {
        dim3 grid(OUT_FEAT / 128, (N_NODES + 127) / 128);
        gemm_f16_kernel<HID, OUT_FEAT, true>
            <<<grid, 256, GEMM_SMEM>>>(hh, hl, W2th, W2tl, bm, out, N_NODES);
    }
}

// round 12
// speedup vs baseline: 1.8409x; 1.0649x over previous
#include <cuda_runtime.h>
#include <cuda_fp16.h>
#include <cstdint>

#define N_NODES  50000
#define N_EDGES  1600000
#define IN_FEAT  256
#define HID      128
#define OUT_FEAT 256
#define N_YZ     256              // [y | z] width

// ---------------------------------------------------------------------------
// Device scratch
// ---------------------------------------------------------------------------
__device__ __half g_y16 [N_NODES * HID];         // y fp16 (12.8 MB)
__device__ float  g_z   [N_NODES * HID];         // z fp32 (25.6 MB)
__device__ __half g_xh  [N_NODES * IN_FEAT];     // x split hi
__device__ __half g_xl  [N_NODES * IN_FEAT];     // x split lo
__device__ __half g_hh  [N_NODES * HID];         // h split hi
__device__ __half g_hl  [N_NODES * HID];         // h split lo
__device__ __half g_W1th[N_YZ * IN_FEAT];        // [We|Wn]^T hi  [256][256]
__device__ __half g_W1tl[N_YZ * IN_FEAT];        // [We|Wn]^T lo
__device__ __half g_W2th[OUT_FEAT * HID];        // Wm^T hi       [256][128]
__device__ __half g_W2tl[OUT_FEAT * HID];        // Wm^T lo
__device__ float  g_hb  [HID];                   // b_node + b_edge
// CSR-by-dst
__device__ int    g_cnt [N_NODES];               // histogram, then cursor
__device__ int    g_off [N_NODES + 1];
__device__ int2   g_edge[N_EDGES];               // {src, w_bits}

// ---------------------------------------------------------------------------
// helpers
// ---------------------------------------------------------------------------
__device__ __forceinline__ void split_h(float v, __half& hi, __half& lo) {
    hi = __float2half_rn(v);
    lo = __float2half_rn(v - __half2float(hi));
}
__device__ __forceinline__ uint32_t packh(__half a, __half b) {
    __half2 h2 = __halves2half2(a, b);
    return *(uint32_t*)&h2;
}
__device__ __forceinline__ uint32_t smem_u32(const void* p) {
    uint32_t a;
    asm("{ .reg .u64 t; cvta.to.shared.u64 t, %1; cvt.u32.u64 %0, t; }"
        : "=r"(a) : "l"(p));
    return a;
}
#define CP_ASYNC16(dst, src, sz) \
    asm volatile("cp.async.cg.shared.global [%0], [%1], 16, %2;" \
                 :: "r"(dst), "l"(src), "r"(sz) : "memory")
#define CP_COMMIT()  asm volatile("cp.async.commit_group;" ::: "memory")
#define CP_WAIT1()   asm volatile("cp.async.wait_group 1;"  ::: "memory")

// ---------------------------------------------------------------------------
// CSR build: zero -> hist -> scan -> scatter
// ---------------------------------------------------------------------------
__global__ void zero_cnt_kernel() {
    int i = blockIdx.x * blockDim.x + threadIdx.x;
    if (i < N_NODES) g_cnt[i] = 0;
}

__global__ void hist_kernel(const int* __restrict__ dst) {
    int e = blockIdx.x * blockDim.x + threadIdx.x;
    if (e < N_EDGES) atomicAdd(&g_cnt[dst[e]], 1);
}

__global__ __launch_bounds__(1024) void scan_kernel() {
    __shared__ int part[1024];
    const int tid = threadIdx.x;
    const int C = (N_NODES + 1023) / 1024;          // 49
    const int base = tid * C;
    int s = 0;
    for (int j = 0; j < C; ++j) {
        int i = base + j;
        if (i < N_NODES) s += g_cnt[i];
    }
    part[tid] = s;
    __syncthreads();
    for (int d = 1; d < 1024; d <<= 1) {            // Hillis-Steele inclusive
        int v = 0;
        if (tid >= d) v = part[tid - d];
        __syncthreads();
        if (tid >= d) part[tid] += v;
        __syncthreads();
    }
    int run = (tid == 0) ? 0 : part[tid - 1];
    for (int j = 0; j < C; ++j) {
        int i = base + j;
        if (i < N_NODES) {
            int c = g_cnt[i];
            g_off[i] = run;
            g_cnt[i] = run;                          // cursor for scatter
            run += c;
        }
    }
    if (tid == 0) g_off[N_NODES] = part[1023];
}

__global__ void scatter_kernel(const int* __restrict__ src,
                               const int* __restrict__ dst,
                               const float* __restrict__ w) {
    int e = blockIdx.x * blockDim.x + threadIdx.x;
    if (e >= N_EDGES) return;
    int d = dst[e];
    int p = atomicAdd(&g_cnt[d], 1);
    g_edge[p] = make_int2(src[e], __float_as_int(w[e]));
}

// ---------------------------------------------------------------------------
// pre-split x into fp16 hi/lo
// ---------------------------------------------------------------------------
__global__ void split_x_kernel(const float4* __restrict__ x4) {
    int i = blockIdx.x * blockDim.x + threadIdx.x;
    if (i >= N_NODES * IN_FEAT / 4) return;
    float4 v = x4[i];
    __half h0, l0, h1, l1, h2, l2, h3, l3;
    split_h(v.x, h0, l0); split_h(v.y, h1, l1);
    split_h(v.z, h2, l2); split_h(v.w, h3, l3);
    uint2 H = make_uint2(packh(h0, h1), packh(h2, h3));
    uint2 L = make_uint2(packh(l0, l1), packh(l2, l3));
    *(uint2*)&g_xh[i * 4] = H;
    *(uint2*)&g_xl[i * 4] = L;
}

// ---------------------------------------------------------------------------
// weight transposes (fp16-split)
// ---------------------------------------------------------------------------
__global__ void fold_w1t_kernel(const float* __restrict__ We,
                                const float* __restrict__ Wn) {
    int idx = blockIdx.x * blockDim.x + threadIdx.x;
    if (idx >= N_YZ * IN_FEAT) return;
    int n = idx >> 8;            // 0..255
    int k = idx & 255;           // 0..255
    float v = (n < HID) ? We[(size_t)k * HID + n]
                        : Wn[(size_t)k * HID + (n - HID)];
    __half h, l;
    split_h(v, h, l);
    g_W1th[(size_t)n * IN_FEAT + k] = h;
    g_W1tl[(size_t)n * IN_FEAT + k] = l;
}

__global__ void fold_w2t_kernel(const float* __restrict__ Wm,
                                const float* __restrict__ bn,
                                const float* __restrict__ be) {
    int idx = blockIdx.x * blockDim.x + threadIdx.x;
    if (idx < OUT_FEAT * HID) {
        int n = idx >> 7;        // 0..255
        int k = idx & 127;       // 0..127
        float v = Wm[(size_t)k * OUT_FEAT + n];
        __half h, l;
        split_h(v, h, l);
        g_W2th[(size_t)n * HID + k] = h;
        g_W2tl[(size_t)n * HID + k] = l;
    }
    if (idx < HID) g_hb[idx] = bn[idx] + be[idx];
}

// ---------------------------------------------------------------------------
// CSR aggregation + h fusion: one warp per node, no atomics.
//   h[v] = z[v] + sum_e y[src_e]*w_e + hb ;  output split fp16 hi/lo
// y is fp16: a row = 128 halfs = 256 B = 16 x uint4. Lanes split into two
// half-warps (by bit 4); each half-warp covers a full row (16 lanes x 16B,
// LDG.128 kept) and processes alternating edges; one shfl_xor(16) merges.
// ---------------------------------------------------------------------------
__global__ __launch_bounds__(256) void agg_csr_kernel() {
    int v    = (blockIdx.x * blockDim.x + threadIdx.x) >> 5;
    int lane = threadIdx.x & 31;
    if (v >= N_NODES) return;

    const int half_id = lane >> 4;       // 0 or 1
    const int l16     = lane & 15;       // covers cols l16*8 .. l16*8+7

    int b  = g_off[v];
    int e2 = g_off[v + 1];
    const uint4* yb = (const uint4*)g_y16;   // 16 uint4 per row

    float acc[8];
    #pragma unroll
    for (int j = 0; j < 8; ++j) acc[j] = 0.f;

    for (int i = b + half_id; i < e2; i += 2) {
        int2 e = g_edge[i];
        float wgt = __int_as_float(e.y);
        uint4 q = yb[(size_t)e.x * 16 + l16];
        float2 f0 = __half22float2(*(const __half2*)&q.x);
        float2 f1 = __half22float2(*((const __half2*)&q.x + 1));
        float2 f2 = __half22float2(*(const __half2*)&q.z);
        float2 f3 = __half22float2(*((const __half2*)&q.z + 1));
        acc[0] = fmaf(f0.x, wgt, acc[0]);
        acc[1] = fmaf(f0.y, wgt, acc[1]);
        acc[2] = fmaf(f1.x, wgt, acc[2]);
        acc[3] = fmaf(f1.y, wgt, acc[3]);
        acc[4] = fmaf(f2.x, wgt, acc[4]);
        acc[5] = fmaf(f2.y, wgt, acc[5]);
        acc[6] = fmaf(f3.x, wgt, acc[6]);
        acc[7] = fmaf(f3.y, wgt, acc[7]);
    }
    // merge the two half-warp partial sums (same cols in lanes L and L+16)
    #pragma unroll
    for (int j = 0; j < 8; ++j)
        acc[j] += __shfl_xor_sync(0xffffffffu, acc[j], 16);

    // add z + hb for cols l16*8 .. +7
    const float4* zp  = (const float4*)(g_z  + (size_t)v * HID + l16 * 8);
    const float4* hbp = (const float4*)(g_hb + l16 * 8);
    float4 z0 = zp[0],  z1 = zp[1];
    float4 h0 = hbp[0], h1 = hbp[1];
    acc[0] += z0.x + h0.x;  acc[1] += z0.y + h0.y;
    acc[2] += z0.z + h0.z;  acc[3] += z0.w + h0.w;
    acc[4] += z1.x + h1.x;  acc[5] += z1.y + h1.y;
    acc[6] += z1.z + h1.z;  acc[7] += z1.w + h1.w;

    // split and store: half 0 writes hi, half 1 writes lo (both have full sums)
    __half hs[8], ls[8];
    #pragma unroll
    for (int j = 0; j < 8; ++j) split_h(acc[j], hs[j], ls[j]);
    uint4 pkt;
    if (half_id == 0) {
        pkt.x = packh(hs[0], hs[1]); pkt.y = packh(hs[2], hs[3]);
        pkt.z = packh(hs[4], hs[5]); pkt.w = packh(hs[6], hs[7]);
    } else {
        pkt.x = packh(ls[0], ls[1]); pkt.y = packh(ls[2], ls[3]);
        pkt.z = packh(ls[4], ls[5]); pkt.w = packh(ls[6], ls[7]);
    }
    __half* base = half_id ? g_hl : g_hh;
    *(uint4*)(base + (size_t)v * HID + l16 * 8) = pkt;
}

// ---------------------------------------------------------------------------
// split-precision fp16 GEMM, cp.async double-buffered (R9/R11-validated core).
// C = A @ Bt^T (+ bias); A,Bt pre-split fp16; A row stride = KTOT.
// YZ variant: column-block 0 writes fp16 y, block 1 writes fp32 z (stride HID).
// BM=128, BN=128, BK=32; 256 threads; warp tile 32x64; mma.m16n8k16.
// ---------------------------------------------------------------------------
#define MMA_F16(C, A, B0, B1)                                               \
    asm volatile(                                                           \
        "mma.sync.aligned.m16n8k16.row.col.f32.f16.f16.f32 "                \
        "{%0,%1,%2,%3}, {%4,%5,%6,%7}, {%8,%9}, {%0,%1,%2,%3};"             \
        : "+f"((C)[0]), "+f"((C)[1]), "+f"((C)[2]), "+f"((C)[3])            \
        : "r"((A)[0]), "r"((A)[1]), "r"((A)[2]), "r"((A)[3]),               \
          "r"(B0), "r"(B1))

#define STAGE_BYTES 40960
#define GEMM_SMEM   (2 * STAGE_BYTES)

template<int KTOT, int NOUT, bool BIAS, bool YZ>
__global__ __launch_bounds__(256) void gemm_f16_kernel(
    const __half* __restrict__ Ah, const __half* __restrict__ Al,   // [M x KTOT]
    const __half* __restrict__ Bh, const __half* __restrict__ Bl,   // [NOUT x KTOT]
    const float*  __restrict__ bias,
    float*        __restrict__ Cf,     // fp32 out (or z when YZ)
    __half*       __restrict__ Ch,     // fp16 y out (YZ only)
    int M) {
    extern __shared__ uint32_t sm[];
    const uint32_t smb = smem_u32(sm);

    const int tid  = threadIdx.x;
    const int brow = blockIdx.y * 128;
    const int bcol = blockIdx.x * 128;

    const int warp = tid >> 5, lane = tid & 31;
    const int g = lane >> 2, tg = lane & 3;
    const int wm = warp >> 1, wn = warp & 1;

    constexpr int T = KTOT / 32;

    float acc[2][8][4];
    #pragma unroll
    for (int mt = 0; mt < 2; ++mt)
        #pragma unroll
        for (int nt = 0; nt < 8; ++nt)
            #pragma unroll
            for (int i = 0; i < 4; ++i) acc[mt][nt][i] = 0.f;

    auto issue = [&](int t) {
        const int s  = t & 1;
        const uint32_t sb = smb + s * STAGE_BYTES;
        const int k0 = t * 32;
        #pragma unroll
        for (int i = 0; i < 2; ++i) {
            int ch = tid + i * 256;       // 0..511
            int m = ch >> 2, c = ch & 3;
            // ---- A ----
            int r = brow + m;
            uint32_t sz = (r < M) ? 16u : 0u;
            int rc = (r < M) ? r : (M - 1);
            size_t oa = (size_t)rc * KTOT + k0 + c * 8;
            uint32_t da = sb + (uint32_t)(m * 20 + c * 4) * 4;
            CP_ASYNC16(da,          Ah + oa, sz);
            CP_ASYNC16(da + 10240,  Al + oa, sz);
            // ---- B ----
            int n = bcol + m;
            size_t ob = (size_t)n * KTOT + k0 + c * 8;
            CP_ASYNC16(da + 20480, Bh + ob, 16u);
            CP_ASYNC16(da + 30720, Bl + ob, 16u);
        }
    };

    issue(0); CP_COMMIT();
    if (T > 1) issue(1);
    CP_COMMIT();

    for (int t = 0; t < T; ++t) {
        CP_WAIT1();
        __syncthreads();

        const uint32_t* Ash = sm + (t & 1) * (STAGE_BYTES / 4);
        const uint32_t* Asl = Ash + 2560;
        const uint32_t* Bsh = Ash + 5120;
        const uint32_t* Bsl = Ash + 7680;

        #pragma unroll
        for (int ks2 = 0; ks2 < 2; ++ks2) {
            const int kb = ks2 * 8;
            uint32_t afh[2][4], afl[2][4];
            #pragma unroll
            for (int mt = 0; mt < 2; ++mt) {
                int m0 = wm * 32 + mt * 16 + g;
                int o00 = m0 * 20 + kb + tg;
                int o10 = (m0 + 8) * 20 + kb + tg;
                afh[mt][0] = Ash[o00];     afl[mt][0] = Asl[o00];
                afh[mt][1] = Ash[o10];     afl[mt][1] = Asl[o10];
                afh[mt][2] = Ash[o00 + 4]; afl[mt][2] = Asl[o00 + 4];
                afh[mt][3] = Ash[o10 + 4]; afl[mt][3] = Asl[o10 + 4];
            }
            #pragma unroll
            for (int nt = 0; nt < 8; ++nt) {
                int n = wn * 64 + nt * 8 + g;
                int ob = n * 20 + kb + tg;
                uint32_t bh0 = Bsh[ob], bh1 = Bsh[ob + 4];
                uint32_t bl0 = Bsl[ob], bl1 = Bsl[ob + 4];
                #pragma unroll
                for (int mt = 0; mt < 2; ++mt) {
                    MMA_F16(acc[mt][nt], afh[mt], bh0, bh1);
                    MMA_F16(acc[mt][nt], afl[mt], bh0, bh1);
                    MMA_F16(acc[mt][nt], afh[mt], bl0, bl1);
                }
            }
        }
        __syncthreads();
        if (t + 2 < T) issue(t + 2);
        CP_COMMIT();
    }

    // ---- epilogue ----
    const bool y_block = YZ && (blockIdx.x == 0);
    #pragma unroll
    for (int mt = 0; mt < 2; ++mt) {
        int row0 = brow + wm * 32 + mt * 16 + g;
        int row1 = row0 + 8;
        #pragma unroll
        for (int nt = 0; nt < 8; ++nt) {
            int lcol = wn * 64 + nt * 8 + tg * 2;        // 0..127 within block
            if (y_block) {
                if (row0 < M)
                    *(__half2*)(Ch + (size_t)row0 * HID + lcol) =
                        __floats2half2_rn(acc[mt][nt][0], acc[mt][nt][1]);
                if (row1 < M)
                    *(__half2*)(Ch + (size_t)row1 * HID + lcol) =
                        __floats2half2_rn(acc[mt][nt][2], acc[mt][nt][3]);
            } else {
                const int stride = YZ ? HID : NOUT;       // z stride = HID
                const int col    = YZ ? lcol : (bcol + lcol);
                float b0 = BIAS ? bias[col]     : 0.f;
                float b1 = BIAS ? bias[col + 1] : 0.f;
                if (row0 < M) {
                    float2 o = make_float2(acc[mt][nt][0] + b0, acc[mt][nt][1] + b1);
                    *(float2*)(Cf + (size_t)row0 * stride + col) = o;
                }
                if (row1 < M) {
                    float2 o = make_float2(acc[mt][nt][2] + b0, acc[mt][nt][3] + b1);
                    *(float2*)(Cf + (size_t)row1 * stride + col) = o;
                }
            }
        }
    }
}

// ---------------------------------------------------------------------------
// launch
// ---------------------------------------------------------------------------
extern "C" void kernel_launch(void* const* d_in, const int* in_sizes, int n_in,
                              void* d_out, int out_size) {
    const float* x   = (const float*)d_in[0];
    const float* w   = (const float*)d_in[1];
    const int*   src = (const int*)  d_in[2];
    const int*   dst = (const int*)  d_in[3];
    const float* Wn  = (const float*)d_in[4];
    const float* bn  = (const float*)d_in[5];
    const float* We  = (const float*)d_in[6];
    const float* be  = (const float*)d_in[7];
    const float* Wm  = (const float*)d_in[8];
    const float* bm  = (const float*)d_in[9];
    float*       out = (float*)d_out;

    float *z;
    __half *y16, *xh, *xl, *hh, *hl, *W1th, *W1tl, *W2th, *W2tl;
    cudaGetSymbolAddress((void**)&y16,  g_y16);
    cudaGetSymbolAddress((void**)&z,    g_z);
    cudaGetSymbolAddress((void**)&xh,   g_xh);
    cudaGetSymbolAddress((void**)&xl,   g_xl);
    cudaGetSymbolAddress((void**)&hh,   g_hh);
    cudaGetSymbolAddress((void**)&hl,   g_hl);
    cudaGetSymbolAddress((void**)&W1th, g_W1th);
    cudaGetSymbolAddress((void**)&W1tl, g_W1tl);
    cudaGetSymbolAddress((void**)&W2th, g_W2th);
    cudaGetSymbolAddress((void**)&W2tl, g_W2tl);

    cudaFuncSetAttribute(gemm_f16_kernel<IN_FEAT, N_YZ, false, true>,
                         cudaFuncAttributeMaxDynamicSharedMemorySize, GEMM_SMEM);
    cudaFuncSetAttribute(gemm_f16_kernel<HID, OUT_FEAT, true, false>,
                         cudaFuncAttributeMaxDynamicSharedMemorySize, GEMM_SMEM);

    // CSR build
    zero_cnt_kernel<<<(N_NODES + 255) / 256, 256>>>();
    hist_kernel<<<(N_EDGES + 255) / 256, 256>>>(dst);
    scan_kernel<<<1, 1024>>>();
    scatter_kernel<<<(N_EDGES + 255) / 256, 256>>>(src, dst, w);

    // pre-split x; transpose+split weights
    split_x_kernel<<<(N_NODES * IN_FEAT / 4 + 255) / 256, 256>>>((const float4*)x);
    fold_w1t_kernel<<<(N_YZ * IN_FEAT + 255) / 256, 256>>>(We, Wn);
    fold_w2t_kernel<<<(OUT_FEAT * HID + 255) / 256, 256>>>(Wm, bn, be);

    // GEMM1: [y|z] = x @ [We|Wn];  y -> fp16, z -> fp32
    {
        dim3 grid(N_YZ / 128, (N_NODES + 127) / 128);
        gemm_f16_kernel<IN_FEAT, N_YZ, false, true>
            <<<grid, 256, GEMM_SMEM>>>(xh, xl, W1th, W1tl, nullptr, z, y16, N_NODES);
    }

    // agg: h = z + sum y[src]*w + (bn+be)  -> split fp16
    agg_csr_kernel<<<(N_NODES * 32 + 255) / 256, 256>>>();

    // GEMM2: out = h @ Wm + bm   [50000 x 256] fp32
    {
        dim3 grid(OUT_FEAT / 128, (N_NODES + 127) / 128);
        gemm_f16_kernel<HID, OUT_FEAT, true, false>
            <<<grid, 256, GEMM_SMEM>>>(hh, hl, W2th, W2tl, bm, out, nullptr, N_NODES);
    }
}

// round 14
// speedup vs baseline: 2.4555x; 1.3338x over previous
#include <cuda_runtime.h>
#include <cuda_fp16.h>
#include <cstdint>

#define N_NODES  50000
#define N_EDGES  1600000
#define IN_FEAT  256
#define HID      128
#define OUT_FEAT 256
#define N_YZ     256              // [y | z] width

// ---------------------------------------------------------------------------
// Device scratch
// ---------------------------------------------------------------------------
__device__ __half g_y16 [N_NODES * HID];         // y fp16 (12.8 MB)
__device__ float  g_z   [N_NODES * HID];         // z fp32 (25.6 MB)
__device__ __half g_xh  [N_NODES * IN_FEAT];     // x split hi
__device__ __half g_xl  [N_NODES * IN_FEAT];     // x split lo
__device__ __half g_hh  [N_NODES * HID];         // h split hi
__device__ __half g_hl  [N_NODES * HID];         // h split lo
__device__ __half g_W1th[N_YZ * IN_FEAT];        // [We|Wn]^T hi  [256][256]
__device__ __half g_W1tl[N_YZ * IN_FEAT];        // [We|Wn]^T lo
__device__ __half g_W2th[OUT_FEAT * HID];        // Wm^T hi       [256][128]
__device__ __half g_W2tl[OUT_FEAT * HID];        // Wm^T lo
__device__ float  g_hb  [HID];                   // b_node + b_edge
// CSR-by-dst
__device__ int    g_cnt [N_NODES];               // histogram, then cursor
__device__ int    g_off [N_NODES + 1];
__device__ int2   g_edge[N_EDGES];               // {src, w_bits}

// ---------------------------------------------------------------------------
// helpers
// ---------------------------------------------------------------------------
__device__ __forceinline__ void split_h(float v, __half& hi, __half& lo) {
    hi = __float2half_rn(v);
    lo = __float2half_rn(v - __half2float(hi));
}
__device__ __forceinline__ uint32_t packh(__half a, __half b) {
    __half2 h2 = __halves2half2(a, b);
    return *(uint32_t*)&h2;
}
__device__ __forceinline__ uint32_t smem_u32(const void* p) {
    uint32_t a;
    asm("{ .reg .u64 t; cvta.to.shared.u64 t, %1; cvt.u32.u64 %0, t; }"
        : "=r"(a) : "l"(p));
    return a;
}
#define CP_ASYNC16(dst, src, sz) \
    asm volatile("cp.async.cg.shared.global [%0], [%1], 16, %2;" \
                 :: "r"(dst), "l"(src), "r"(sz) : "memory")
#define CP_COMMIT()  asm volatile("cp.async.commit_group;" ::: "memory")
#define CP_WAIT1()   asm volatile("cp.async.wait_group 1;"  ::: "memory")

// ---------------------------------------------------------------------------
// CSR build: zero -> hist -> scan -> scatter
// ---------------------------------------------------------------------------
__global__ void zero_cnt_kernel() {
    int i = blockIdx.x * blockDim.x + threadIdx.x;
    if (i < N_NODES) g_cnt[i] = 0;
}

__global__ void hist_kernel(const int* __restrict__ dst) {
    int e = blockIdx.x * blockDim.x + threadIdx.x;
    if (e < N_EDGES) atomicAdd(&g_cnt[dst[e]], 1);
}

__global__ __launch_bounds__(1024) void scan_kernel() {
    __shared__ int part[1024];
    const int tid = threadIdx.x;
    const int C = (N_NODES + 1023) / 1024;          // 49
    const int base = tid * C;
    int s = 0;
    for (int j = 0; j < C; ++j) {
        int i = base + j;
        if (i < N_NODES) s += g_cnt[i];
    }
    part[tid] = s;
    __syncthreads();
    for (int d = 1; d < 1024; d <<= 1) {            // Hillis-Steele inclusive
        int v = 0;
        if (tid >= d) v = part[tid - d];
        __syncthreads();
        if (tid >= d) part[tid] += v;
        __syncthreads();
    }
    int run = (tid == 0) ? 0 : part[tid - 1];
    for (int j = 0; j < C; ++j) {
        int i = base + j;
        if (i < N_NODES) {
            int c = g_cnt[i];
            g_off[i] = run;
            g_cnt[i] = run;                          // cursor for scatter
            run += c;
        }
    }
    if (tid == 0) g_off[N_NODES] = part[1023];
}

__global__ void scatter_kernel(const int* __restrict__ src,
                               const int* __restrict__ dst,
                               const float* __restrict__ w) {
    int e = blockIdx.x * blockDim.x + threadIdx.x;
    if (e >= N_EDGES) return;
    int d = dst[e];
    int p = atomicAdd(&g_cnt[d], 1);
    g_edge[p] = make_int2(src[e], __float_as_int(w[e]));
}

// ---------------------------------------------------------------------------
// pre-split x into fp16 hi/lo
// ---------------------------------------------------------------------------
__global__ void split_x_kernel(const float4* __restrict__ x4) {
    int i = blockIdx.x * blockDim.x + threadIdx.x;
    if (i >= N_NODES * IN_FEAT / 4) return;
    float4 v = x4[i];
    __half h0, l0, h1, l1, h2, l2, h3, l3;
    split_h(v.x, h0, l0); split_h(v.y, h1, l1);
    split_h(v.z, h2, l2); split_h(v.w, h3, l3);
    uint2 H = make_uint2(packh(h0, h1), packh(h2, h3));
    uint2 L = make_uint2(packh(l0, l1), packh(l2, l3));
    *(uint2*)&g_xh[i * 4] = H;
    *(uint2*)&g_xl[i * 4] = L;
}

// ---------------------------------------------------------------------------
// weight transposes (fp16-split)
// ---------------------------------------------------------------------------
__global__ void fold_w1t_kernel(const float* __restrict__ We,
                                const float* __restrict__ Wn) {
    int idx = blockIdx.x * blockDim.x + threadIdx.x;
    if (idx >= N_YZ * IN_FEAT) return;
    int n = idx >> 8;            // 0..255
    int k = idx & 255;           // 0..255
    float v = (n < HID) ? We[(size_t)k * HID + n]
                        : Wn[(size_t)k * HID + (n - HID)];
    __half h, l;
    split_h(v, h, l);
    g_W1th[(size_t)n * IN_FEAT + k] = h;
    g_W1tl[(size_t)n * IN_FEAT + k] = l;
}

__global__ void fold_w2t_kernel(const float* __restrict__ Wm,
                                const float* __restrict__ bn,
                                const float* __restrict__ be) {
    int idx = blockIdx.x * blockDim.x + threadIdx.x;
    if (idx < OUT_FEAT * HID) {
        int n = idx >> 7;        // 0..255
        int k = idx & 127;       // 0..127
        float v = Wm[(size_t)k * OUT_FEAT + n];
        __half h, l;
        split_h(v, h, l);
        g_W2th[(size_t)n * HID + k] = h;
        g_W2tl[(size_t)n * HID + k] = l;
    }
    if (idx < HID) g_hb[idx] = bn[idx] + be[idx];
}

// ---------------------------------------------------------------------------
// CSR aggregation + h fusion: one warp per node, no atomics.
//   h[v] = z[v] + sum_e y[src_e]*w_e + hb ;  output split fp16 hi/lo
// y is fp16: a row = 128 halfs = 256 B = 16 x uint4. Lanes split into two
// half-warps (by bit 4); each half-warp covers a full row (16 lanes x 16B,
// LDG.128 kept) and processes alternating edges; one shfl_xor(16) merges.
// ---------------------------------------------------------------------------
__global__ __launch_bounds__(256) void agg_csr_kernel() {
    int v    = (blockIdx.x * blockDim.x + threadIdx.x) >> 5;
    int lane = threadIdx.x & 31;
    if (v >= N_NODES) return;

    const int half_id = lane >> 4;       // 0 or 1
    const int l16     = lane & 15;       // covers cols l16*8 .. l16*8+7

    int b  = g_off[v];
    int e2 = g_off[v + 1];
    const uint4* yb = (const uint4*)g_y16;   // 16 uint4 per row

    float acc[8];
    #pragma unroll
    for (int j = 0; j < 8; ++j) acc[j] = 0.f;

    for (int i = b + half_id; i < e2; i += 2) {
        int2 e = g_edge[i];
        float wgt = __int_as_float(e.y);
        uint4 q = yb[(size_t)e.x * 16 + l16];
        float2 f0 = __half22float2(*(const __half2*)&q.x);
        float2 f1 = __half22float2(*((const __half2*)&q.x + 1));
        float2 f2 = __half22float2(*(const __half2*)&q.z);
        float2 f3 = __half22float2(*((const __half2*)&q.z + 1));
        acc[0] = fmaf(f0.x, wgt, acc[0]);
        acc[1] = fmaf(f0.y, wgt, acc[1]);
        acc[2] = fmaf(f1.x, wgt, acc[2]);
        acc[3] = fmaf(f1.y, wgt, acc[3]);
        acc[4] = fmaf(f2.x, wgt, acc[4]);
        acc[5] = fmaf(f2.y, wgt, acc[5]);
        acc[6] = fmaf(f3.x, wgt, acc[6]);
        acc[7] = fmaf(f3.y, wgt, acc[7]);
    }
    // merge the two half-warp partial sums (same cols in lanes L and L+16)
    #pragma unroll
    for (int j = 0; j < 8; ++j)
        acc[j] += __shfl_xor_sync(0xffffffffu, acc[j], 16);

    // add z + hb for cols l16*8 .. +7
    const float4* zp  = (const float4*)(g_z  + (size_t)v * HID + l16 * 8);
    const float4* hbp = (const float4*)(g_hb + l16 * 8);
    float4 z0 = zp[0],  z1 = zp[1];
    float4 h0 = hbp[0], h1 = hbp[1];
    acc[0] += z0.x + h0.x;  acc[1] += z0.y + h0.y;
    acc[2] += z0.z + h0.z;  acc[3] += z0.w + h0.w;
    acc[4] += z1.x + h1.x;  acc[5] += z1.y + h1.y;
    acc[6] += z1.z + h1.z;  acc[7] += z1.w + h1.w;

    // split and store: half 0 writes hi, half 1 writes lo (both have full sums)
    __half hs[8], ls[8];
    #pragma unroll
    for (int j = 0; j < 8; ++j) split_h(acc[j], hs[j], ls[j]);
    uint4 pkt;
    if (half_id == 0) {
        pkt.x = packh(hs[0], hs[1]); pkt.y = packh(hs[2], hs[3]);
        pkt.z = packh(hs[4], hs[5]); pkt.w = packh(hs[6], hs[7]);
    } else {
        pkt.x = packh(ls[0], ls[1]); pkt.y = packh(ls[2], ls[3]);
        pkt.z = packh(ls[4], ls[5]); pkt.w = packh(ls[6], ls[7]);
    }
    __half* base = half_id ? g_hl : g_hh;
    *(uint4*)(base + (size_t)v * HID + l16 * 8) = pkt;
}

// ---------------------------------------------------------------------------
// split-precision fp16 GEMM, cp.async double-buffered (R9/R11-validated core).
// C = A @ Bt^T (+ bias); A,Bt pre-split fp16; A row stride = KTOT.
// YZ variant: column-block 0 writes fp16 y, block 1 writes fp32 z (stride HID).
// BM=128, BN=128, BK=32; 256 threads; warp tile 32x64; mma.m16n8k16.
// ---------------------------------------------------------------------------
#define MMA_F16(C, A, B0, B1)                                               \
    asm volatile(                                                           \
        "mma.sync.aligned.m16n8k16.row.col.f32.f16.f16.f32 "                \
        "{%0,%1,%2,%3}, {%4,%5,%6,%7}, {%8,%9}, {%0,%1,%2,%3};"             \
        : "+f"((C)[0]), "+f"((C)[1]), "+f"((C)[2]), "+f"((C)[3])            \
        : "r"((A)[0]), "r"((A)[1]), "r"((A)[2]), "r"((A)[3]),               \
          "r"(B0), "r"(B1))

#define STAGE_BYTES 40960
#define GEMM_SMEM   (2 * STAGE_BYTES)

template<int KTOT, int NOUT, bool BIAS, bool YZ>
__global__ __launch_bounds__(256) void gemm_f16_kernel(
    const __half* __restrict__ Ah, const __half* __restrict__ Al,   // [M x KTOT]
    const __half* __restrict__ Bh, const __half* __restrict__ Bl,   // [NOUT x KTOT]
    const float*  __restrict__ bias,
    float*        __restrict__ Cf,     // fp32 out (or z when YZ)
    __half*       __restrict__ Ch,     // fp16 y out (YZ only)
    int M) {
    extern __shared__ uint32_t sm[];
    const uint32_t smb = smem_u32(sm);

    const int tid  = threadIdx.x;
    const int brow = blockIdx.y * 128;
    const int bcol = blockIdx.x * 128;

    const int warp = tid >> 5, lane = tid & 31;
    const int g = lane >> 2, tg = lane & 3;
    const int wm = warp >> 1, wn = warp & 1;

    constexpr int T = KTOT / 32;

    float acc[2][8][4];
    #pragma unroll
    for (int mt = 0; mt < 2; ++mt)
        #pragma unroll
        for (int nt = 0; nt < 8; ++nt)
            #pragma unroll
            for (int i = 0; i < 4; ++i) acc[mt][nt][i] = 0.f;

    auto issue = [&](int t) {
        const int s  = t & 1;
        const uint32_t sb = smb + s * STAGE_BYTES;
        const int k0 = t * 32;
        #pragma unroll
        for (int i = 0; i < 2; ++i) {
            int ch = tid + i * 256;       // 0..511
            int m = ch >> 2, c = ch & 3;
            // ---- A ----
            int r = brow + m;
            uint32_t sz = (r < M) ? 16u : 0u;
            int rc = (r < M) ? r : (M - 1);
            size_t oa = (size_t)rc * KTOT + k0 + c * 8;
            uint32_t da = sb + (uint32_t)(m * 20 + c * 4) * 4;
            CP_ASYNC16(da,          Ah + oa, sz);
            CP_ASYNC16(da + 10240,  Al + oa, sz);
            // ---- B ----
            int n = bcol + m;
            size_t ob = (size_t)n * KTOT + k0 + c * 8;
            CP_ASYNC16(da + 20480, Bh + ob, 16u);
            CP_ASYNC16(da + 30720, Bl + ob, 16u);
        }
    };

    issue(0); CP_COMMIT();
    if (T > 1) issue(1);
    CP_COMMIT();

    for (int t = 0; t < T; ++t) {
        CP_WAIT1();
        __syncthreads();

        const uint32_t* Ash = sm + (t & 1) * (STAGE_BYTES / 4);
        const uint32_t* Asl = Ash + 2560;
        const uint32_t* Bsh = Ash + 5120;
        const uint32_t* Bsl = Ash + 7680;

        #pragma unroll
        for (int ks2 = 0; ks2 < 2; ++ks2) {
            const int kb = ks2 * 8;
            uint32_t afh[2][4], afl[2][4];
            #pragma unroll
            for (int mt = 0; mt < 2; ++mt) {
                int m0 = wm * 32 + mt * 16 + g;
                int o00 = m0 * 20 + kb + tg;
                int o10 = (m0 + 8) * 20 + kb + tg;
                afh[mt][0] = Ash[o00];     afl[mt][0] = Asl[o00];
                afh[mt][1] = Ash[o10];     afl[mt][1] = Asl[o10];
                afh[mt][2] = Ash[o00 + 4]; afl[mt][2] = Asl[o00 + 4];
                afh[mt][3] = Ash[o10 + 4]; afl[mt][3] = Asl[o10 + 4];
            }
            #pragma unroll
            for (int nt = 0; nt < 8; ++nt) {
                int n = wn * 64 + nt * 8 + g;
                int ob = n * 20 + kb + tg;
                uint32_t bh0 = Bsh[ob], bh1 = Bsh[ob + 4];
                uint32_t bl0 = Bsl[ob], bl1 = Bsl[ob + 4];
                #pragma unroll
                for (int mt = 0; mt < 2; ++mt) {
                    MMA_F16(acc[mt][nt], afh[mt], bh0, bh1);
                    MMA_F16(acc[mt][nt], afl[mt], bh0, bh1);
                    MMA_F16(acc[mt][nt], afh[mt], bl0, bl1);
                }
            }
        }
        __syncthreads();
        if (t + 2 < T) issue(t + 2);
        CP_COMMIT();
    }

    // ---- epilogue ----
    const bool y_block = YZ && (blockIdx.x == 0);
    #pragma unroll
    for (int mt = 0; mt < 2; ++mt) {
        int row0 = brow + wm * 32 + mt * 16 + g;
        int row1 = row0 + 8;
        #pragma unroll
        for (int nt = 0; nt < 8; ++nt) {
            int lcol = wn * 64 + nt * 8 + tg * 2;        // 0..127 within block
            if (y_block) {
                if (row0 < M)
                    *(__half2*)(Ch + (size_t)row0 * HID + lcol) =
                        __floats2half2_rn(acc[mt][nt][0], acc[mt][nt][1]);
                if (row1 < M)
                    *(__half2*)(Ch + (size_t)row1 * HID + lcol) =
                        __floats2half2_rn(acc[mt][nt][2], acc[mt][nt][3]);
            } else {
                const int stride = YZ ? HID : NOUT;       // z stride = HID
                const int col    = YZ ? lcol : (bcol + lcol);
                float b0 = BIAS ? bias[col]     : 0.f;
                float b1 = BIAS ? bias[col + 1] : 0.f;
                if (row0 < M) {
                    float2 o = make_float2(acc[mt][nt][0] + b0, acc[mt][nt][1] + b1);
                    *(float2*)(Cf + (size_t)row0 * stride + col) = o;
                }
                if (row1 < M) {
                    float2 o = make_float2(acc[mt][nt][2] + b0, acc[mt][nt][3] + b1);
                    *(float2*)(Cf + (size_t)row1 * stride + col) = o;
                }
            }
        }
    }
}

// ---------------------------------------------------------------------------
// launch — CSR build forked onto a side stream, overlapping the dense chain.
// Capture-safe fork: event on the (captured) default stream -> side stream
// waits -> CSR chain -> event -> default stream waits before agg.
// Streams/events are host objects (not device memory); they are created per
// call and intentionally not destroyed (a capturing stream cannot be
// destroyed inside the capture region).
// ---------------------------------------------------------------------------
extern "C" void kernel_launch(void* const* d_in, const int* in_sizes, int n_in,
                              void* d_out, int out_size) {
    const float* x   = (const float*)d_in[0];
    const float* w   = (const float*)d_in[1];
    const int*   src = (const int*)  d_in[2];
    const int*   dst = (const int*)  d_in[3];
    const float* Wn  = (const float*)d_in[4];
    const float* bn  = (const float*)d_in[5];
    const float* We  = (const float*)d_in[6];
    const float* be  = (const float*)d_in[7];
    const float* Wm  = (const float*)d_in[8];
    const float* bm  = (const float*)d_in[9];
    float*       out = (float*)d_out;

    float *z;
    __half *y16, *xh, *xl, *hh, *hl, *W1th, *W1tl, *W2th, *W2tl;
    cudaGetSymbolAddress((void**)&y16,  g_y16);
    cudaGetSymbolAddress((void**)&z,    g_z);
    cudaGetSymbolAddress((void**)&xh,   g_xh);
    cudaGetSymbolAddress((void**)&xl,   g_xl);
    cudaGetSymbolAddress((void**)&hh,   g_hh);
    cudaGetSymbolAddress((void**)&hl,   g_hl);
    cudaGetSymbolAddress((void**)&W1th, g_W1th);
    cudaGetSymbolAddress((void**)&W1tl, g_W1tl);
    cudaGetSymbolAddress((void**)&W2th, g_W2th);
    cudaGetSymbolAddress((void**)&W2tl, g_W2tl);

    cudaFuncSetAttribute(gemm_f16_kernel<IN_FEAT, N_YZ, false, true>,
                         cudaFuncAttributeMaxDynamicSharedMemorySize, GEMM_SMEM);
    cudaFuncSetAttribute(gemm_f16_kernel<HID, OUT_FEAT, true, false>,
                         cudaFuncAttributeMaxDynamicSharedMemorySize, GEMM_SMEM);

    // fork resources (created per call; see header comment)
    cudaStream_t s2;
    cudaStreamCreateWithFlags(&s2, cudaStreamNonBlocking);
    cudaEvent_t eFork, eJoin;
    cudaEventCreateWithFlags(&eFork, cudaEventDisableTiming);
    cudaEventCreateWithFlags(&eJoin, cudaEventDisableTiming);

    // ---- fork: CSR build on side stream ----
    cudaEventRecord(eFork, 0);
    cudaStreamWaitEvent(s2, eFork, 0);
    zero_cnt_kernel<<<(N_NODES + 255) / 256, 256, 0, s2>>>();
    hist_kernel<<<(N_EDGES + 255) / 256, 256, 0, s2>>>(dst);
    scan_kernel<<<1, 1024, 0, s2>>>();
    scatter_kernel<<<(N_EDGES + 255) / 256, 256, 0, s2>>>(src, dst, w);
    cudaEventRecord(eJoin, s2);

    // ---- dense chain on main stream (overlaps CSR build) ----
    split_x_kernel<<<(N_NODES * IN_FEAT / 4 + 255) / 256, 256>>>((const float4*)x);
    fold_w1t_kernel<<<(N_YZ * IN_FEAT + 255) / 256, 256>>>(We, Wn);
    fold_w2t_kernel<<<(OUT_FEAT * HID + 255) / 256, 256>>>(Wm, bn, be);

    // GEMM1: [y|z] = x @ [We|Wn];  y -> fp16, z -> fp32
    {
        dim3 grid(N_YZ / 128, (N_NODES + 127) / 128);
        gemm_f16_kernel<IN_FEAT, N_YZ, false, true>
            <<<grid, 256, GEMM_SMEM>>>(xh, xl, W1th, W1tl, nullptr, z, y16, N_NODES);
    }

    // ---- join: agg needs CSR + GEMM1 ----
    cudaStreamWaitEvent(0, eJoin, 0);

    // agg: h = z + sum y[src]*w + (bn+be)  -> split fp16
    agg_csr_kernel<<<(N_NODES * 32 + 255) / 256, 256>>>();

    // GEMM2: out = h @ Wm + bm   [50000 x 256] fp32
    {
        dim3 grid(OUT_FEAT / 128, (N_NODES + 127) / 128);
        gemm_f16_kernel<HID, OUT_FEAT, true, false>
            <<<grid, 256, GEMM_SMEM>>>(hh, hl, W2th, W2tl, bm, out, nullptr, N_NODES);
    }
}